// round 3
// baseline (speedup 1.0000x reference)
#include <cuda_runtime.h>
#include <math.h>

#define BATCH  16
#define CCH    256
#define HWSZ   1024
#define NHEAD  8
#define HDIM   32
#define NGROUP 8
#define GN_EPS 1e-5f
#define ATTN_SCALE 0.17677669529663687f   /* 1/sqrt(32) */

// ---------------- scratch (no allocations allowed) ----------------
__device__ float  g_qkv [3 * BATCH * NHEAD * HWSZ * HDIM];   // [t][b][head][s][d]  (~50 MB)
__device__ float  g_attn[BATCH * CCH * HWSZ];                // attention out, [b][c][s]
__device__ float  g_proj[BATCH * CCH * HWSZ];                // proj out, [b][c][s]
__device__ float2 g_stats[BATCH * NGROUP];                   // (mean, rstd) per (b,g)

// =====================================================================
// GEMM: out[o][s] = sum_c W[o][c] * X[b][c][s]
// block tile 128x128, K-tile 16, 8x8 per thread (split halves for
// conflict-free float4 smem reads).
// mode 0: W = w_qkv (M=768), X = input x, writes g_qkv in [t][b][h][s][d]
// mode 1: W = w_proj (M=256), X = g_attn,  writes g_proj in [b][c][s]
// =====================================================================
__global__ __launch_bounds__(256) void gemm_kernel(const float* __restrict__ W,
                                                   const float* __restrict__ Xext,
                                                   int mode)
{
    __shared__ float As[16 * 132];   // As[k][o]  (transposed W tile)
    __shared__ float Bs[16 * 132];   // Bs[k][s]

    const int tid = threadIdx.x;
    const int b   = blockIdx.z;
    const int s0  = blockIdx.y * 128;
    const int o0  = blockIdx.x * 128;
    const int t_o = tid & 15;
    const int t_s = tid >> 4;

    const float* Xb = (mode == 0 ? Xext : g_attn) + b * (CCH * HWSZ);

    float acc[2][4][2][4];
#pragma unroll
    for (int a = 0; a < 2; a++)
#pragma unroll
        for (int i = 0; i < 4; i++)
#pragma unroll
            for (int c = 0; c < 2; c++)
#pragma unroll
                for (int j = 0; j < 4; j++) acc[a][i][c][j] = 0.f;

    for (int kt = 0; kt < 16; kt++) {
        __syncthreads();
#pragma unroll
        for (int i = 0; i < 8; i++) {
            int idx = i * 256 + tid;
            int o = idx >> 4, k = idx & 15;
            As[k * 132 + o] = W[(o0 + o) * CCH + kt * 16 + k];
        }
#pragma unroll
        for (int i = 0; i < 8; i++) {
            int idx = i * 256 + tid;
            int k = idx >> 7, s = idx & 127;
            Bs[k * 132 + s] = Xb[(kt * 16 + k) * HWSZ + s0 + s];
        }
        __syncthreads();
#pragma unroll
        for (int k = 0; k < 16; k++) {
            float4 a0 = *(const float4*)&As[k * 132 + t_o * 4];
            float4 a1 = *(const float4*)&As[k * 132 + 64 + t_o * 4];
            float4 b0 = *(const float4*)&Bs[k * 132 + t_s * 4];
            float4 b1 = *(const float4*)&Bs[k * 132 + 64 + t_s * 4];
            float av[8] = {a0.x, a0.y, a0.z, a0.w, a1.x, a1.y, a1.z, a1.w};
            float bv[8] = {b0.x, b0.y, b0.z, b0.w, b1.x, b1.y, b1.z, b1.w};
#pragma unroll
            for (int oh = 0; oh < 2; oh++)
#pragma unroll
                for (int i = 0; i < 4; i++)
#pragma unroll
                    for (int jh = 0; jh < 2; jh++)
#pragma unroll
                        for (int j = 0; j < 4; j++)
                            acc[oh][i][jh][j] += av[oh * 4 + i] * bv[jh * 4 + j];
        }
    }

    if (mode == 0) {
        // write g_qkv[t][b][head][s][d]; 4 consecutive o = 4 consecutive d
#pragma unroll
        for (int jh = 0; jh < 2; jh++)
#pragma unroll
            for (int j = 0; j < 4; j++) {
                int s = s0 + jh * 64 + t_s * 4 + j;
#pragma unroll
                for (int oh = 0; oh < 2; oh++) {
                    int og    = o0 + oh * 64 + t_o * 4;
                    int t_idx = og >> 8;
                    int head  = (og >> 5) & 7;
                    int d0    = og & 31;
                    float4 v = make_float4(acc[oh][0][jh][j], acc[oh][1][jh][j],
                                           acc[oh][2][jh][j], acc[oh][3][jh][j]);
                    float* dst = g_qkv +
                        (((t_idx * BATCH + b) * NHEAD + head) * HWSZ + s) * HDIM + d0;
                    *(float4*)dst = v;
                }
            }
    } else {
        // plain [b][c][s] layout, float4 along s
#pragma unroll
        for (int oh = 0; oh < 2; oh++)
#pragma unroll
            for (int i = 0; i < 4; i++) {
                int o = o0 + oh * 64 + t_o * 4 + i;
                float* row = g_proj + (b * CCH + o) * HWSZ + s0;
#pragma unroll
                for (int jh = 0; jh < 2; jh++) {
                    float4 v = make_float4(acc[oh][i][jh][0], acc[oh][i][jh][1],
                                           acc[oh][i][jh][2], acc[oh][i][jh][3]);
                    *(float4*)(row + jh * 64 + t_s * 4) = v;
                }
            }
    }
}

// =====================================================================
// Flash attention, fp32. One block per (q-tile 128, head, b).
// smem: Qs[32][132] (d-major) | KVs (K:[32][132] d-major / V:[128][32]) |
//       Ss[128][132] | m[128] l[128] rescale[128]    -> 102912 B dynamic.
// S-gemm: 16(t_j) x 16(t_r) threads, 8x8 each (split halves).
// PV:     8(t_d) x 32(t_r2) threads, 4 rows x 4 dims each, O in regs.
// =====================================================================
#define ATTN_SMEM_FLOATS (32*132 + 32*132 + 128*132 + 3*128)
#define ATTN_SMEM_BYTES  (ATTN_SMEM_FLOATS * 4)

__global__ __launch_bounds__(256, 2) void attn_kernel()
{
    extern __shared__ float sm[];
    float* Qs  = sm;                      // 4224
    float* KVs = sm + 32 * 132;           // 4224 (K transposed or V natural)
    float* Ss  = sm + 2 * 32 * 132;       // 16896
    float* m_s = Ss + 128 * 132;
    float* l_s = m_s + 128;
    float* rsc = l_s + 128;

    const int tid  = threadIdx.x;
    const int b    = blockIdx.z;
    const int head = blockIdx.y;
    const int q0   = blockIdx.x * 128;
    const int t_j  = tid & 15, t_r  = tid >> 4;
    const int t_d  = tid & 7,  t_r2 = tid >> 3;

    const float* Qg = g_qkv + ((0 * BATCH + b) * NHEAD + head) * (HWSZ * HDIM);
    const float* Kg = g_qkv + ((1 * BATCH + b) * NHEAD + head) * (HWSZ * HDIM);
    const float* Vg = g_qkv + ((2 * BATCH + b) * NHEAD + head) * (HWSZ * HDIM);

    if (tid < 128) { m_s[tid] = -INFINITY; l_s[tid] = 0.f; }

    // load Q tile transposed: Qs[d][r]
#pragma unroll
    for (int i = 0; i < 16; i++) {
        int idx = i * 256 + tid;
        int r = idx >> 5, d = idx & 31;
        Qs[d * 132 + r] = Qg[(q0 + r) * HDIM + d];
    }

    float O[4][4] = {};

    for (int kt = 0; kt < 8; kt++) {
        __syncthreads();   // prev PV done (KVs/Ss free); covers Q load/stat init on kt=0
        // load K tile transposed: KVs[d][j]
#pragma unroll
        for (int i = 0; i < 16; i++) {
            int idx = i * 256 + tid;
            int jj = idx >> 5, d = idx & 31;
            KVs[d * 132 + jj] = Kg[(kt * 128 + jj) * HDIM + d];
        }
        __syncthreads();

        // ---- S = Q K^T ----
        float acc[2][4][2][4];
#pragma unroll
        for (int a = 0; a < 2; a++)
#pragma unroll
            for (int i = 0; i < 4; i++)
#pragma unroll
                for (int c = 0; c < 2; c++)
#pragma unroll
                    for (int j = 0; j < 4; j++) acc[a][i][c][j] = 0.f;

#pragma unroll 8
        for (int d = 0; d < 32; d++) {
            float4 a0 = *(const float4*)&Qs[d * 132 + t_r * 4];
            float4 a1 = *(const float4*)&Qs[d * 132 + 64 + t_r * 4];
            float4 k0 = *(const float4*)&KVs[d * 132 + t_j * 4];
            float4 k1 = *(const float4*)&KVs[d * 132 + 64 + t_j * 4];
            float av[8] = {a0.x, a0.y, a0.z, a0.w, a1.x, a1.y, a1.z, a1.w};
            float kv[8] = {k0.x, k0.y, k0.z, k0.w, k1.x, k1.y, k1.z, k1.w};
#pragma unroll
            for (int ih = 0; ih < 2; ih++)
#pragma unroll
                for (int i = 0; i < 4; i++)
#pragma unroll
                    for (int jh = 0; jh < 2; jh++)
#pragma unroll
                        for (int j = 0; j < 4; j++)
                            acc[ih][i][jh][j] += av[ih * 4 + i] * kv[jh * 4 + j];
        }

        // ---- online softmax (row owned by one half-warp) ----
#pragma unroll
        for (int ih = 0; ih < 2; ih++)
#pragma unroll
            for (int i = 0; i < 4; i++) {
                int r = ih * 64 + t_r * 4 + i;
                float mold = m_s[r];
                float vmax = -INFINITY;
#pragma unroll
                for (int jh = 0; jh < 2; jh++)
#pragma unroll
                    for (int j = 0; j < 4; j++) {
                        acc[ih][i][jh][j] *= ATTN_SCALE;
                        vmax = fmaxf(vmax, acc[ih][i][jh][j]);
                    }
#pragma unroll
                for (int m = 1; m < 16; m <<= 1)
                    vmax = fmaxf(vmax, __shfl_xor_sync(0xffffffffu, vmax, m));
                float mnew = fmaxf(mold, vmax);
                float sum = 0.f;
#pragma unroll
                for (int jh = 0; jh < 2; jh++) {
                    float4 pv;
                    pv.x = __expf(acc[ih][i][jh][0] - mnew);
                    pv.y = __expf(acc[ih][i][jh][1] - mnew);
                    pv.z = __expf(acc[ih][i][jh][2] - mnew);
                    pv.w = __expf(acc[ih][i][jh][3] - mnew);
                    sum += pv.x + pv.y + pv.z + pv.w;
                    *(float4*)&Ss[r * 132 + jh * 64 + t_j * 4] = pv;
                }
#pragma unroll
                for (int m = 1; m < 16; m <<= 1)
                    sum += __shfl_xor_sync(0xffffffffu, sum, m);
                if (t_j == 0) {
                    float alpha = __expf(mold - mnew);
                    l_s[r] = l_s[r] * alpha + sum;
                    m_s[r] = mnew;
                    rsc[r] = alpha;
                }
            }
        __syncthreads();   // Ks reads done; Ss + rsc published

        // load V tile natural layout: KVs[j][d] (overwrites K)
#pragma unroll
        for (int i = 0; i < 4; i++) {
            int idx = i * 256 + tid;
            ((float4*)KVs)[idx] = ((const float4*)Vg)[kt * 1024 + idx];
        }
        // rescale running O
#pragma unroll
        for (int rr = 0; rr < 4; rr++) {
            float a = rsc[t_r2 * 4 + rr];
#pragma unroll
            for (int dd = 0; dd < 4; dd++) O[rr][dd] *= a;
        }
        __syncthreads();   // V visible

        // ---- O += P V ----
#pragma unroll 4
        for (int j0 = 0; j0 < 128; j0 += 4) {
            float4 p[4], v[4];
#pragma unroll
            for (int rr = 0; rr < 4; rr++)
                p[rr] = *(const float4*)&Ss[(t_r2 * 4 + rr) * 132 + j0];
#pragma unroll
            for (int jj = 0; jj < 4; jj++)
                v[jj] = *(const float4*)&KVs[(j0 + jj) * 32 + t_d * 4];
#pragma unroll
            for (int rr = 0; rr < 4; rr++) {
                float pj[4] = {p[rr].x, p[rr].y, p[rr].z, p[rr].w};
#pragma unroll
                for (int jj = 0; jj < 4; jj++) {
                    O[rr][0] += pj[jj] * v[jj].x;
                    O[rr][1] += pj[jj] * v[jj].y;
                    O[rr][2] += pj[jj] * v[jj].z;
                    O[rr][3] += pj[jj] * v[jj].w;
                }
            }
        }
    }

    // normalize + write [b][c][s] (float4 along s)
    float inv[4];
#pragma unroll
    for (int rr = 0; rr < 4; rr++) inv[rr] = 1.f / l_s[t_r2 * 4 + rr];
#pragma unroll
    for (int dd = 0; dd < 4; dd++) {
        float4 o4 = make_float4(O[0][dd] * inv[0], O[1][dd] * inv[1],
                                O[2][dd] * inv[2], O[3][dd] * inv[3]);
        float* dst = g_attn + (size_t)(b * CCH + head * HDIM + t_d * 4 + dd) * HWSZ
                     + q0 + t_r2 * 4;
        *(float4*)dst = o4;
    }
}

// =====================================================================
// GroupNorm stats: one block per (b,g); group data is contiguous 32768 floats
// =====================================================================
__global__ __launch_bounds__(256) void gn_stats_kernel()
{
    __shared__ float rs[8], rs2[8];
    int bg = blockIdx.x;
    const float4* p = (const float4*)(g_proj + (size_t)bg * 32 * HWSZ);
    float s = 0.f, s2 = 0.f;
    for (int i = threadIdx.x; i < 8192; i += 256) {
        float4 v = p[i];
        s  += v.x + v.y + v.z + v.w;
        s2 += v.x * v.x + v.y * v.y + v.z * v.z + v.w * v.w;
    }
#pragma unroll
    for (int m = 16; m >= 1; m >>= 1) {
        s  += __shfl_xor_sync(0xffffffffu, s, m);
        s2 += __shfl_xor_sync(0xffffffffu, s2, m);
    }
    int lane = threadIdx.x & 31, w = threadIdx.x >> 5;
    if (lane == 0) { rs[w] = s; rs2[w] = s2; }
    __syncthreads();
    if (threadIdx.x == 0) {
        float S = 0.f, S2 = 0.f;
#pragma unroll
        for (int i = 0; i < 8; i++) { S += rs[i]; S2 += rs2[i]; }
        float mean = S * (1.f / 32768.f);
        float var  = S2 * (1.f / 32768.f) - mean * mean;
        g_stats[bg] = make_float2(mean, rsqrtf(var + GN_EPS));
    }
}

// =====================================================================
// normalize + affine + residual
// =====================================================================
__global__ __launch_bounds__(256) void apply_kernel(const float4* __restrict__ x,
                                                    const float* __restrict__ gamma,
                                                    const float* __restrict__ beta,
                                                    float4* __restrict__ out)
{
    int i = blockIdx.x * 256 + threadIdx.x;   // over 1,048,576 float4s
    int lin = i << 2;
    int c   = (lin >> 10) & 255;
    int bg  = lin >> 15;
    float2 st = g_stats[bg];
    float ga = gamma[c] * st.y;
    float be = beta[c];
    float4 pv = ((const float4*)g_proj)[i];
    float4 xv = x[i];
    float4 o;
    o.x = (pv.x - st.x) * ga + be + xv.x;
    o.y = (pv.y - st.x) * ga + be + xv.y;
    o.z = (pv.z - st.x) * ga + be + xv.z;
    o.w = (pv.w - st.x) * ga + be + xv.w;
    out[i] = o;
}

// =====================================================================
extern "C" void kernel_launch(void* const* d_in, const int* in_sizes, int n_in,
                              void* d_out, int out_size)
{
    const float* x      = (const float*)d_in[0];
    const float* w_qkv  = (const float*)d_in[1];
    const float* w_proj = (const float*)d_in[2];
    const float* gamma  = (const float*)d_in[3];
    const float* beta   = (const float*)d_in[4];
    float* out = (float*)d_out;

    cudaFuncSetAttribute(attn_kernel, cudaFuncAttributeMaxDynamicSharedMemorySize,
                         ATTN_SMEM_BYTES);

    gemm_kernel<<<dim3(6, 8, 16), 256>>>(w_qkv, x, 0);              // QKV
    attn_kernel<<<dim3(8, 8, 16), 256, ATTN_SMEM_BYTES>>>();        // attention
    gemm_kernel<<<dim3(2, 8, 16), 256>>>(w_proj, x, 1);             // proj
    gn_stats_kernel<<<128, 256>>>();                                // GN stats
    apply_kernel<<<4096, 256>>>((const float4*)x, gamma, beta,      // GN + residual
                                (float4*)out);
}

// round 8
// speedup vs baseline: 1.6460x; 1.6460x over previous
#include <cuda_runtime.h>
#include <math.h>
#include <stdint.h>

#define BATCH  16
#define CCH    256
#define HWSZ   1024
#define NHEAD  8
#define HDIM   32
#define NGROUP 8
#define GN_EPS 1e-5f
#define ATTN_SCALE 0.17677669529663687f   /* 1/sqrt(32) */

// ---------------- scratch (no allocations allowed) ----------------
__device__ float  g_qkv [3 * BATCH * NHEAD * HWSZ * HDIM];   // [t][b][head][s][d]
__device__ float  g_attn[BATCH * CCH * HWSZ];                // attention out, [b][c][s]
__device__ float  g_proj[BATCH * CCH * HWSZ];                // proj out, [b][c][s]
__device__ float2 g_stats[BATCH * NGROUP];                   // (mean, rstd) per (b,g)

// =====================================================================
// fp32 GEMM: out[o][s] = sum_c W[o][c] * X[b][c][s]   (unchanged, proven)
// =====================================================================
__global__ __launch_bounds__(256) void gemm_kernel(const float* __restrict__ W,
                                                   const float* __restrict__ Xext,
                                                   int mode)
{
    __shared__ float As[16 * 132];
    __shared__ float Bs[16 * 132];

    const int tid = threadIdx.x;
    const int b   = blockIdx.z;
    const int s0  = blockIdx.y * 128;
    const int o0  = blockIdx.x * 128;
    const int t_o = tid & 15;
    const int t_s = tid >> 4;

    const float* Xb = (mode == 0 ? Xext : g_attn) + b * (CCH * HWSZ);

    float acc[2][4][2][4];
#pragma unroll
    for (int a = 0; a < 2; a++)
#pragma unroll
        for (int i = 0; i < 4; i++)
#pragma unroll
            for (int c = 0; c < 2; c++)
#pragma unroll
                for (int j = 0; j < 4; j++) acc[a][i][c][j] = 0.f;

    for (int kt = 0; kt < 16; kt++) {
        __syncthreads();
#pragma unroll
        for (int i = 0; i < 8; i++) {
            int idx = i * 256 + tid;
            int o = idx >> 4, k = idx & 15;
            As[k * 132 + o] = W[(o0 + o) * CCH + kt * 16 + k];
        }
#pragma unroll
        for (int i = 0; i < 8; i++) {
            int idx = i * 256 + tid;
            int k = idx >> 7, s = idx & 127;
            Bs[k * 132 + s] = Xb[(kt * 16 + k) * HWSZ + s0 + s];
        }
        __syncthreads();
#pragma unroll
        for (int k = 0; k < 16; k++) {
            float4 a0 = *(const float4*)&As[k * 132 + t_o * 4];
            float4 a1 = *(const float4*)&As[k * 132 + 64 + t_o * 4];
            float4 b0 = *(const float4*)&Bs[k * 132 + t_s * 4];
            float4 b1 = *(const float4*)&Bs[k * 132 + 64 + t_s * 4];
            float av[8] = {a0.x, a0.y, a0.z, a0.w, a1.x, a1.y, a1.z, a1.w};
            float bv[8] = {b0.x, b0.y, b0.z, b0.w, b1.x, b1.y, b1.z, b1.w};
#pragma unroll
            for (int oh = 0; oh < 2; oh++)
#pragma unroll
                for (int i = 0; i < 4; i++)
#pragma unroll
                    for (int jh = 0; jh < 2; jh++)
#pragma unroll
                        for (int j = 0; j < 4; j++)
                            acc[oh][i][jh][j] += av[oh * 4 + i] * bv[jh * 4 + j];
        }
    }

    if (mode == 0) {
#pragma unroll
        for (int jh = 0; jh < 2; jh++)
#pragma unroll
            for (int j = 0; j < 4; j++) {
                int s = s0 + jh * 64 + t_s * 4 + j;
#pragma unroll
                for (int oh = 0; oh < 2; oh++) {
                    int og    = o0 + oh * 64 + t_o * 4;
                    int t_idx = og >> 8;
                    int head  = (og >> 5) & 7;
                    int d0    = og & 31;
                    float4 v = make_float4(acc[oh][0][jh][j], acc[oh][1][jh][j],
                                           acc[oh][2][jh][j], acc[oh][3][jh][j]);
                    float* dst = g_qkv +
                        (((t_idx * BATCH + b) * NHEAD + head) * HWSZ + s) * HDIM + d0;
                    *(float4*)dst = v;
                }
            }
    } else {
#pragma unroll
        for (int oh = 0; oh < 2; oh++)
#pragma unroll
            for (int i = 0; i < 4; i++) {
                int o = o0 + oh * 64 + t_o * 4 + i;
                float* row = g_proj + (b * CCH + o) * HWSZ + s0;
#pragma unroll
                for (int jh = 0; jh < 2; jh++) {
                    float4 v = make_float4(acc[oh][i][jh][0], acc[oh][i][jh][1],
                                           acc[oh][i][jh][2], acc[oh][i][jh][3]);
                    *(float4*)(row + jh * 64 + t_s * 4) = v;
                }
            }
    }
}

// =====================================================================
// tf32 tensor-core helpers
// =====================================================================
__device__ __forceinline__ uint32_t f2tf(float x) {
    uint32_t r;
    asm volatile("cvt.rna.tf32.f32 %0, %1;" : "=r"(r) : "f"(x));
    return r;
}

__device__ __forceinline__ void mma_tf32(float4& c,
                                         uint32_t a0, uint32_t a1, uint32_t a2, uint32_t a3,
                                         uint32_t b0, uint32_t b1) {
    asm volatile("mma.sync.aligned.m16n8k8.row.col.f32.tf32.tf32.f32 "
                 "{%0,%1,%2,%3}, {%4,%5,%6,%7}, {%8,%9}, {%0,%1,%2,%3};\n"
                 : "+f"(c.x), "+f"(c.y), "+f"(c.z), "+f"(c.w)
                 : "r"(a0), "r"(a1), "r"(a2), "r"(a3), "r"(b0), "r"(b1));
}

// =====================================================================
// Flash attention, tf32 mma.sync m16n8k8, fp32 softmax.
// Fragment layout per PTX / CUTLASS SM80_16x8x8_F32TF32TF32F32_TN:
//   A: a0=(g,t) a1=(g+8,t) a2=(g,t+4) a3=(g+8,t+4)
//   B: b0=(k=t,n=g) b1=(k=t+4,n=g)
//   C: c0=(g,2t) c1=(g,2t+1) c2=(g+8,2t) c3=(g+8,2t+1)
// Pitches (conflict-free on hot fragment loads):
//   Ks[128][36], Vs[128][40], Ss[128][132]
// FIX vs R4: in-loop K/V staging now covers ALL 128 rows
//   (was r = st_r + i*64, i<2 -> rows 32-63 / 96-127 stale garbage)
// =====================================================================
#define KS_PITCH 36
#define VS_PITCH 40
#define SS_PITCH 132
#define ATTN_SMEM_WORDS (128 * (KS_PITCH + VS_PITCH + SS_PITCH))
#define ATTN_SMEM_BYTES (ATTN_SMEM_WORDS * 4)

__global__ __launch_bounds__(256, 2) void attn_kernel()
{
    extern __shared__ uint32_t smu[];
    uint32_t* Ks = smu;
    uint32_t* Vs = smu + 128 * KS_PITCH;
    uint32_t* Ss = smu + 128 * (KS_PITCH + VS_PITCH);
    float*    Ssf = (float*)Ss;

    const int tid  = threadIdx.x;
    const int warp = tid >> 5;
    const int lane = tid & 31;
    const int lr   = lane >> 2;   // groupID 0..7
    const int lc   = lane & 3;    // threadID_in_group 0..3

    const int b    = blockIdx.z;
    const int head = blockIdx.y;
    const int q0   = blockIdx.x * 128;

    const float* Qg = g_qkv + ((0 * BATCH + b) * NHEAD + head) * (HWSZ * HDIM);
    const float* Kg = g_qkv + ((1 * BATCH + b) * NHEAD + head) * (HWSZ * HDIM);
    const float* Vg = g_qkv + ((2 * BATCH + b) * NHEAD + head) * (HWSZ * HDIM);

    const int st_r  = tid >> 3;          // staging row base 0..31
    const int st_d4 = (tid & 7) * 4;     // staging d offset

    // ---- stage Q (into Ss region, pitch KS_PITCH) and K(0), as tf32 ----
#pragma unroll
    for (int i = 0; i < 4; i++) {
        int idx = i * 256 + tid;
        int r = idx >> 3, d4 = (idx & 7) * 4;
        float4 q = *(const float4*)&Qg[(q0 + r) * HDIM + d4];
        Ss[r * KS_PITCH + d4 + 0] = f2tf(q.x);
        Ss[r * KS_PITCH + d4 + 1] = f2tf(q.y);
        Ss[r * KS_PITCH + d4 + 2] = f2tf(q.z);
        Ss[r * KS_PITCH + d4 + 3] = f2tf(q.w);
        float4 k = *(const float4*)&Kg[r * HDIM + d4];
        Ks[r * KS_PITCH + d4 + 0] = f2tf(k.x);
        Ks[r * KS_PITCH + d4 + 1] = f2tf(k.y);
        Ks[r * KS_PITCH + d4 + 2] = f2tf(k.z);
        Ks[r * KS_PITCH + d4 + 3] = f2tf(k.w);
    }
    __syncthreads();

    // ---- extract Q A-fragments (registers for whole kernel) ----
    const int r0 = warp * 16 + lr;
    uint32_t qa[4][4];
#pragma unroll
    for (int kb = 0; kb < 4; kb++) {
        qa[kb][0] = Ss[(r0)     * KS_PITCH + kb * 8 + lc];        // (g,   t)
        qa[kb][1] = Ss[(r0 + 8) * KS_PITCH + kb * 8 + lc];        // (g+8, t)
        qa[kb][2] = Ss[(r0)     * KS_PITCH + kb * 8 + lc + 4];    // (g,   t+4)
        qa[kb][3] = Ss[(r0 + 8) * KS_PITCH + kb * 8 + lc + 4];    // (g+8, t+4)
    }
    __syncthreads();   // Ss free for P

    float m0 = -INFINITY, m1 = -INFINITY, l0 = 0.f, l1 = 0.f;
    float4 o[4];
#pragma unroll
    for (int nb = 0; nb < 4; nb++) o[nb] = make_float4(0.f, 0.f, 0.f, 0.f);

    for (int kt = 0; kt < 8; kt++) {
        // ---- stage V(kt), ALL 128 rows (fixed) ----
#pragma unroll
        for (int i = 0; i < 4; i++) {
            int r = st_r + i * 32;
            float4 v = *(const float4*)&Vg[(kt * 128 + r) * HDIM + st_d4];
            Vs[r * VS_PITCH + st_d4 + 0] = f2tf(v.x);
            Vs[r * VS_PITCH + st_d4 + 1] = f2tf(v.y);
            Vs[r * VS_PITCH + st_d4 + 2] = f2tf(v.z);
            Vs[r * VS_PITCH + st_d4 + 3] = f2tf(v.w);
        }

        // ---- S = Q K^T  (16 rows x 128 cols per warp) ----
        float4 sacc[16];
#pragma unroll
        for (int nb = 0; nb < 16; nb++) sacc[nb] = make_float4(0.f, 0.f, 0.f, 0.f);
#pragma unroll
        for (int kb = 0; kb < 4; kb++) {
#pragma unroll
            for (int nb = 0; nb < 16; nb++) {
                uint32_t b0 = Ks[(nb * 8 + lr) * KS_PITCH + kb * 8 + lc];       // (k=t,   n=g)
                uint32_t b1 = Ks[(nb * 8 + lr) * KS_PITCH + kb * 8 + lc + 4];   // (k=t+4, n=g)
                mma_tf32(sacc[nb], qa[kb][0], qa[kb][1], qa[kb][2], qa[kb][3], b0, b1);
            }
        }

        // ---- online softmax in registers (rows r0 and r0+8) ----
        float vmax0 = -INFINITY, vmax1 = -INFINITY;
#pragma unroll
        for (int nb = 0; nb < 16; nb++) {
            sacc[nb].x *= ATTN_SCALE; sacc[nb].y *= ATTN_SCALE;
            sacc[nb].z *= ATTN_SCALE; sacc[nb].w *= ATTN_SCALE;
            vmax0 = fmaxf(vmax0, fmaxf(sacc[nb].x, sacc[nb].y));
            vmax1 = fmaxf(vmax1, fmaxf(sacc[nb].z, sacc[nb].w));
        }
#pragma unroll
        for (int m = 1; m < 4; m <<= 1) {
            vmax0 = fmaxf(vmax0, __shfl_xor_sync(0xffffffffu, vmax0, m));
            vmax1 = fmaxf(vmax1, __shfl_xor_sync(0xffffffffu, vmax1, m));
        }
        float mnew0 = fmaxf(m0, vmax0);
        float mnew1 = fmaxf(m1, vmax1);
        float alpha0 = __expf(m0 - mnew0);
        float alpha1 = __expf(m1 - mnew1);
        float sum0 = 0.f, sum1 = 0.f;
#pragma unroll
        for (int nb = 0; nb < 16; nb++) {
            float px = __expf(sacc[nb].x - mnew0);
            float py = __expf(sacc[nb].y - mnew0);
            float pz = __expf(sacc[nb].z - mnew1);
            float pw = __expf(sacc[nb].w - mnew1);
            sum0 += px + py;  sum1 += pz + pw;
            int c0 = nb * 8 + 2 * lc;
            Ss[(r0)     * SS_PITCH + c0]     = f2tf(px);
            Ss[(r0)     * SS_PITCH + c0 + 1] = f2tf(py);
            Ss[(r0 + 8) * SS_PITCH + c0]     = f2tf(pz);
            Ss[(r0 + 8) * SS_PITCH + c0 + 1] = f2tf(pw);
        }
#pragma unroll
        for (int m = 1; m < 4; m <<= 1) {
            sum0 += __shfl_xor_sync(0xffffffffu, sum0, m);
            sum1 += __shfl_xor_sync(0xffffffffu, sum1, m);
        }
        l0 = l0 * alpha0 + sum0;  m0 = mnew0;
        l1 = l1 * alpha1 + sum1;  m1 = mnew1;

        // rescale running O
#pragma unroll
        for (int nb = 0; nb < 4; nb++) {
            o[nb].x *= alpha0; o[nb].y *= alpha0;
            o[nb].z *= alpha1; o[nb].w *= alpha1;
        }
        __syncthreads();   // V visible; all warps done reading Ks

        // ---- stage K(kt+1), ALL 128 rows (fixed) ----
        if (kt < 7) {
#pragma unroll
            for (int i = 0; i < 4; i++) {
                int r = st_r + i * 32;
                float4 k = *(const float4*)&Kg[((kt + 1) * 128 + r) * HDIM + st_d4];
                Ks[r * KS_PITCH + st_d4 + 0] = f2tf(k.x);
                Ks[r * KS_PITCH + st_d4 + 1] = f2tf(k.y);
                Ks[r * KS_PITCH + st_d4 + 2] = f2tf(k.z);
                Ks[r * KS_PITCH + st_d4 + 3] = f2tf(k.w);
            }
        }

        // ---- O += P V  (16 rows x 32 dims per warp, K=128) ----
#pragma unroll
        for (int kb = 0; kb < 16; kb++) {
            uint32_t a0 = Ss[(r0)     * SS_PITCH + kb * 8 + lc];       // (g,   t)
            uint32_t a1 = Ss[(r0 + 8) * SS_PITCH + kb * 8 + lc];       // (g+8, t)
            uint32_t a2 = Ss[(r0)     * SS_PITCH + kb * 8 + lc + 4];   // (g,   t+4)
            uint32_t a3 = Ss[(r0 + 8) * SS_PITCH + kb * 8 + lc + 4];   // (g+8, t+4)
#pragma unroll
            for (int nb = 0; nb < 4; nb++) {
                uint32_t b0 = Vs[(kb * 8 + lc)     * VS_PITCH + nb * 8 + lr];   // (k=t,   n=g)
                uint32_t b1 = Vs[(kb * 8 + lc + 4) * VS_PITCH + nb * 8 + lr];   // (k=t+4, n=g)
                mma_tf32(o[nb], a0, a1, a2, a3, b0, b1);
            }
        }
        __syncthreads();   // PV done: Ss/Vs free; Ks(kt+1) staged
    }

    // ---- epilogue: O /= l, via smem, coalesced write [c][s] ----
    float il0 = 1.f / l0, il1 = 1.f / l1;
#pragma unroll
    for (int nb = 0; nb < 4; nb++) {
        int c0 = nb * 8 + 2 * lc;
        Ssf[(r0)     * 33 + c0]     = o[nb].x * il0;
        Ssf[(r0)     * 33 + c0 + 1] = o[nb].y * il0;
        Ssf[(r0 + 8) * 33 + c0]     = o[nb].z * il1;
        Ssf[(r0 + 8) * 33 + c0 + 1] = o[nb].w * il1;
    }
    __syncthreads();
    float* outb = g_attn + (b * CCH + head * HDIM) * HWSZ + q0;
#pragma unroll
    for (int i = 0; i < 16; i++) {
        int idx = i * 256 + tid;
        int d = idx >> 7, r = idx & 127;
        outb[d * HWSZ + r] = Ssf[r * 33 + d];
    }
}

// =====================================================================
// GroupNorm stats (unchanged)
// =====================================================================
__global__ __launch_bounds__(256) void gn_stats_kernel()
{
    __shared__ float rs[8], rs2[8];
    int bg = blockIdx.x;
    const float4* p = (const float4*)(g_proj + (size_t)bg * 32 * HWSZ);
    float s = 0.f, s2 = 0.f;
    for (int i = threadIdx.x; i < 8192; i += 256) {
        float4 v = p[i];
        s  += v.x + v.y + v.z + v.w;
        s2 += v.x * v.x + v.y * v.y + v.z * v.z + v.w * v.w;
    }
#pragma unroll
    for (int m = 16; m >= 1; m >>= 1) {
        s  += __shfl_xor_sync(0xffffffffu, s, m);
        s2 += __shfl_xor_sync(0xffffffffu, s2, m);
    }
    int lane = threadIdx.x & 31, w = threadIdx.x >> 5;
    if (lane == 0) { rs[w] = s; rs2[w] = s2; }
    __syncthreads();
    if (threadIdx.x == 0) {
        float S = 0.f, S2 = 0.f;
#pragma unroll
        for (int i = 0; i < 8; i++) { S += rs[i]; S2 += rs2[i]; }
        float mean = S * (1.f / 32768.f);
        float var  = S2 * (1.f / 32768.f) - mean * mean;
        g_stats[bg] = make_float2(mean, rsqrtf(var + GN_EPS));
    }
}

// =====================================================================
// normalize + affine + residual (unchanged)
// =====================================================================
__global__ __launch_bounds__(256) void apply_kernel(const float4* __restrict__ x,
                                                    const float* __restrict__ gamma,
                                                    const float* __restrict__ beta,
                                                    float4* __restrict__ out)
{
    int i = blockIdx.x * 256 + threadIdx.x;
    int lin = i << 2;
    int c   = (lin >> 10) & 255;
    int bg  = lin >> 15;
    float2 st = g_stats[bg];
    float ga = gamma[c] * st.y;
    float be = beta[c];
    float4 pv = ((const float4*)g_proj)[i];
    float4 xv = x[i];
    float4 o;
    o.x = (pv.x - st.x) * ga + be + xv.x;
    o.y = (pv.y - st.x) * ga + be + xv.y;
    o.z = (pv.z - st.x) * ga + be + xv.z;
    o.w = (pv.w - st.x) * ga + be + xv.w;
    out[i] = o;
}

// =====================================================================
extern "C" void kernel_launch(void* const* d_in, const int* in_sizes, int n_in,
                              void* d_out, int out_size)
{
    const float* x      = (const float*)d_in[0];
    const float* w_qkv  = (const float*)d_in[1];
    const float* w_proj = (const float*)d_in[2];
    const float* gamma  = (const float*)d_in[3];
    const float* beta   = (const float*)d_in[4];
    float* out = (float*)d_out;

    cudaFuncSetAttribute(attn_kernel, cudaFuncAttributeMaxDynamicSharedMemorySize,
                         ATTN_SMEM_BYTES);

    gemm_kernel<<<dim3(6, 8, 16), 256>>>(w_qkv, x, 0);              // QKV
    attn_kernel<<<dim3(8, 8, 16), 256, ATTN_SMEM_BYTES>>>();        // attention
    gemm_kernel<<<dim3(2, 8, 16), 256>>>(w_proj, x, 1);             // proj
    gn_stats_kernel<<<128, 256>>>();                                // GN stats
    apply_kernel<<<4096, 256>>>((const float4*)x, gamma, beta,      // GN + residual
                                (float4*)out);
}

// round 11
// speedup vs baseline: 2.2839x; 1.3875x over previous
#include <cuda_runtime.h>
#include <math.h>
#include <stdint.h>

#define BATCH  16
#define CCH    256
#define HWSZ   1024
#define NHEAD  8
#define HDIM   32
#define NGROUP 8
#define GN_EPS 1e-5f
#define ATTN_SCALE 0.17677669529663687f   /* 1/sqrt(32) */

// ---------------- scratch (no allocations allowed) ----------------
__device__ float  g_qkv [3 * BATCH * NHEAD * HWSZ * HDIM];   // [t][b][head][s][d]
__device__ float  g_attn[BATCH * CCH * HWSZ];                // attention out, [b][c][s]
__device__ float  g_proj[BATCH * CCH * HWSZ];                // proj out, [b][c][s]
__device__ float2 g_stats[BATCH * NGROUP];                   // (mean, rstd) per (b,g)

// =====================================================================
// tf32 tensor-core helpers (proven in attention kernel)
// =====================================================================
__device__ __forceinline__ uint32_t f2tf(float x) {
    uint32_t r;
    asm volatile("cvt.rna.tf32.f32 %0, %1;" : "=r"(r) : "f"(x));
    return r;
}

__device__ __forceinline__ void mma_tf32(float4& c,
                                         uint32_t a0, uint32_t a1, uint32_t a2, uint32_t a3,
                                         uint32_t b0, uint32_t b1) {
    asm volatile("mma.sync.aligned.m16n8k8.row.col.f32.tf32.tf32.f32 "
                 "{%0,%1,%2,%3}, {%4,%5,%6,%7}, {%8,%9}, {%0,%1,%2,%3};\n"
                 : "+f"(c.x), "+f"(c.y), "+f"(c.z), "+f"(c.w)
                 : "r"(a0), "r"(a1), "r"(a2), "r"(a3), "r"(b0), "r"(b1));
}

// =====================================================================
// tf32 GEMM: out[o][s] = sum_c W[o][c] * X[b][c][s]
// Block tile 128(o) x 128(s), K staged in 8 chunks of 32.
// Warp w owns rows [16w,16w+16) x all 128 cols (same micro-structure as
// the validated attention S-gemm).
// Fragment layout (SM80_16x8x8_F32TF32TF32F32_TN, validated R7):
//   A: a0=(g,t) a1=(g+8,t) a2=(g,t+4) a3=(g+8,t+4)
//   B: b0=(k=t,n=g) b1=(k=t+4,n=g)
//   C: c0=(g,2t) c1=(g,2t+1) c2=(g+8,2t) c3=(g+8,2t+1)
// Pitches: Ws[128][36]  (A-frag bank = 4*lr+lc, bijective)
//          Xs[32][136]  (B-frag bank = 8*lc+lr, bijective)
//          Cs[128][132] epilogue staging (union over Ws+Xs)
// =====================================================================
#define GW_PITCH 36
#define GX_PITCH 136
#define GC_PITCH 132
#define GEMM_SMEM_BYTES (128 * GC_PITCH * 4)   /* 67584 >= stage bufs 35840 */

__global__ __launch_bounds__(256, 2) void gemm_tc_kernel(const float* __restrict__ W,
                                                         const float* __restrict__ Xext,
                                                         int mode)
{
    extern __shared__ uint32_t gsm[];
    uint32_t* Ws = gsm;
    uint32_t* Xs = gsm + 128 * GW_PITCH;
    float*    Cs = (float*)gsm;               // union: valid after k-loop

    const int tid  = threadIdx.x;
    const int warp = tid >> 5;
    const int lane = tid & 31;
    const int lr   = lane >> 2;   // groupID 0..7
    const int lc   = lane & 3;    // threadID_in_group 0..3

    const int b   = blockIdx.z;
    const int s0  = blockIdx.y * 128;
    const int o0  = blockIdx.x * 128;
    const int r0  = warp * 16 + lr;

    const float* Xb = (mode == 0 ? Xext : g_attn) + b * (CCH * HWSZ);

    float4 sacc[16];
#pragma unroll
    for (int nb = 0; nb < 16; nb++) sacc[nb] = make_float4(0.f, 0.f, 0.f, 0.f);

    for (int kc = 0; kc < CCH; kc += 32) {
        __syncthreads();
        // stage W tile: 128 o x 32 k, tf32
#pragma unroll
        for (int i = 0; i < 4; i++) {
            int idx = i * 256 + tid;
            int o = idx >> 3, k4 = (idx & 7) * 4;
            float4 w = *(const float4*)&W[(o0 + o) * CCH + kc + k4];
            Ws[o * GW_PITCH + k4 + 0] = f2tf(w.x);
            Ws[o * GW_PITCH + k4 + 1] = f2tf(w.y);
            Ws[o * GW_PITCH + k4 + 2] = f2tf(w.z);
            Ws[o * GW_PITCH + k4 + 3] = f2tf(w.w);
        }
        // stage X tile: 32 k x 128 s, tf32
#pragma unroll
        for (int i = 0; i < 4; i++) {
            int idx = i * 256 + tid;
            int k = idx >> 5, s4 = (idx & 31) * 4;
            float4 xv = *(const float4*)&Xb[(kc + k) * HWSZ + s0 + s4];
            Xs[k * GX_PITCH + s4 + 0] = f2tf(xv.x);
            Xs[k * GX_PITCH + s4 + 1] = f2tf(xv.y);
            Xs[k * GX_PITCH + s4 + 2] = f2tf(xv.z);
            Xs[k * GX_PITCH + s4 + 3] = f2tf(xv.w);
        }
        __syncthreads();

        // A fragments for this k-chunk
        uint32_t qa[4][4];
#pragma unroll
        for (int kb = 0; kb < 4; kb++) {
            qa[kb][0] = Ws[(r0)     * GW_PITCH + kb * 8 + lc];
            qa[kb][1] = Ws[(r0 + 8) * GW_PITCH + kb * 8 + lc];
            qa[kb][2] = Ws[(r0)     * GW_PITCH + kb * 8 + lc + 4];
            qa[kb][3] = Ws[(r0 + 8) * GW_PITCH + kb * 8 + lc + 4];
        }
#pragma unroll
        for (int kb = 0; kb < 4; kb++) {
#pragma unroll
            for (int nb = 0; nb < 16; nb++) {
                uint32_t b0 = Xs[(kb * 8 + lc)     * GX_PITCH + nb * 8 + lr];
                uint32_t b1 = Xs[(kb * 8 + lc + 4) * GX_PITCH + nb * 8 + lr];
                mma_tf32(sacc[nb], qa[kb][0], qa[kb][1], qa[kb][2], qa[kb][3], b0, b1);
            }
        }
    }
    __syncthreads();   // stage buffers dead; Cs may overwrite

    // stage C tile [o][s] into smem
#pragma unroll
    for (int nb = 0; nb < 16; nb++) {
        int c0 = nb * 8 + 2 * lc;
        Cs[(r0)     * GC_PITCH + c0]     = sacc[nb].x;
        Cs[(r0)     * GC_PITCH + c0 + 1] = sacc[nb].y;
        Cs[(r0 + 8) * GC_PITCH + c0]     = sacc[nb].z;
        Cs[(r0 + 8) * GC_PITCH + c0 + 1] = sacc[nb].w;
    }
    __syncthreads();

    if (mode == 0) {
        // g_qkv[t][b][head][s][d]: float4 along d, 8-thread groups contiguous
#pragma unroll
        for (int i = 0; i < 16; i++) {
            int idx = i * 256 + tid;
            int og = idx & 31;          // o-group of 4
            int s  = idx >> 5;          // 0..127
            int o_abs = o0 + og * 4;
            int t_idx = o_abs >> 8;
            int head  = (o_abs >> 5) & 7;
            int d0    = o_abs & 31;
            float4 v = make_float4(Cs[(og * 4 + 0) * GC_PITCH + s],
                                   Cs[(og * 4 + 1) * GC_PITCH + s],
                                   Cs[(og * 4 + 2) * GC_PITCH + s],
                                   Cs[(og * 4 + 3) * GC_PITCH + s]);
            float* dst = g_qkv +
                (((t_idx * BATCH + b) * NHEAD + head) * HWSZ + (s0 + s)) * HDIM + d0;
            *(float4*)dst = v;
        }
    } else {
        // g_proj[b][c][s]: float4 along s
#pragma unroll
        for (int i = 0; i < 16; i++) {
            int idx = i * 256 + tid;
            int o = idx >> 5, s4 = (idx & 31) * 4;
            float4 v = *(const float4*)&Cs[o * GC_PITCH + s4];
            *(float4*)&g_proj[(b * CCH + o0 + o) * HWSZ + s0 + s4] = v;
        }
    }
}

// =====================================================================
// Flash attention, tf32 mma.sync m16n8k8, fp32 softmax.  (UNCHANGED, R7)
// =====================================================================
#define KS_PITCH 36
#define VS_PITCH 40
#define SS_PITCH 132
#define ATTN_SMEM_WORDS (128 * (KS_PITCH + VS_PITCH + SS_PITCH))
#define ATTN_SMEM_BYTES (ATTN_SMEM_WORDS * 4)

__global__ __launch_bounds__(256, 2) void attn_kernel()
{
    extern __shared__ uint32_t smu[];
    uint32_t* Ks = smu;
    uint32_t* Vs = smu + 128 * KS_PITCH;
    uint32_t* Ss = smu + 128 * (KS_PITCH + VS_PITCH);
    float*    Ssf = (float*)Ss;

    const int tid  = threadIdx.x;
    const int warp = tid >> 5;
    const int lane = tid & 31;
    const int lr   = lane >> 2;
    const int lc   = lane & 3;

    const int b    = blockIdx.z;
    const int head = blockIdx.y;
    const int q0   = blockIdx.x * 128;

    const float* Qg = g_qkv + ((0 * BATCH + b) * NHEAD + head) * (HWSZ * HDIM);
    const float* Kg = g_qkv + ((1 * BATCH + b) * NHEAD + head) * (HWSZ * HDIM);
    const float* Vg = g_qkv + ((2 * BATCH + b) * NHEAD + head) * (HWSZ * HDIM);

    const int st_r  = tid >> 3;
    const int st_d4 = (tid & 7) * 4;

    // stage Q (into Ss region, pitch KS_PITCH) and K(0), tf32
#pragma unroll
    for (int i = 0; i < 4; i++) {
        int idx = i * 256 + tid;
        int r = idx >> 3, d4 = (idx & 7) * 4;
        float4 q = *(const float4*)&Qg[(q0 + r) * HDIM + d4];
        Ss[r * KS_PITCH + d4 + 0] = f2tf(q.x);
        Ss[r * KS_PITCH + d4 + 1] = f2tf(q.y);
        Ss[r * KS_PITCH + d4 + 2] = f2tf(q.z);
        Ss[r * KS_PITCH + d4 + 3] = f2tf(q.w);
        float4 k = *(const float4*)&Kg[r * HDIM + d4];
        Ks[r * KS_PITCH + d4 + 0] = f2tf(k.x);
        Ks[r * KS_PITCH + d4 + 1] = f2tf(k.y);
        Ks[r * KS_PITCH + d4 + 2] = f2tf(k.z);
        Ks[r * KS_PITCH + d4 + 3] = f2tf(k.w);
    }
    __syncthreads();

    const int r0 = warp * 16 + lr;
    uint32_t qa[4][4];
#pragma unroll
    for (int kb = 0; kb < 4; kb++) {
        qa[kb][0] = Ss[(r0)     * KS_PITCH + kb * 8 + lc];
        qa[kb][1] = Ss[(r0 + 8) * KS_PITCH + kb * 8 + lc];
        qa[kb][2] = Ss[(r0)     * KS_PITCH + kb * 8 + lc + 4];
        qa[kb][3] = Ss[(r0 + 8) * KS_PITCH + kb * 8 + lc + 4];
    }
    __syncthreads();

    float m0 = -INFINITY, m1 = -INFINITY, l0 = 0.f, l1 = 0.f;
    float4 o[4];
#pragma unroll
    for (int nb = 0; nb < 4; nb++) o[nb] = make_float4(0.f, 0.f, 0.f, 0.f);

    for (int kt = 0; kt < 8; kt++) {
#pragma unroll
        for (int i = 0; i < 4; i++) {
            int r = st_r + i * 32;
            float4 v = *(const float4*)&Vg[(kt * 128 + r) * HDIM + st_d4];
            Vs[r * VS_PITCH + st_d4 + 0] = f2tf(v.x);
            Vs[r * VS_PITCH + st_d4 + 1] = f2tf(v.y);
            Vs[r * VS_PITCH + st_d4 + 2] = f2tf(v.z);
            Vs[r * VS_PITCH + st_d4 + 3] = f2tf(v.w);
        }

        float4 sacc[16];
#pragma unroll
        for (int nb = 0; nb < 16; nb++) sacc[nb] = make_float4(0.f, 0.f, 0.f, 0.f);
#pragma unroll
        for (int kb = 0; kb < 4; kb++) {
#pragma unroll
            for (int nb = 0; nb < 16; nb++) {
                uint32_t b0 = Ks[(nb * 8 + lr) * KS_PITCH + kb * 8 + lc];
                uint32_t b1 = Ks[(nb * 8 + lr) * KS_PITCH + kb * 8 + lc + 4];
                mma_tf32(sacc[nb], qa[kb][0], qa[kb][1], qa[kb][2], qa[kb][3], b0, b1);
            }
        }

        float vmax0 = -INFINITY, vmax1 = -INFINITY;
#pragma unroll
        for (int nb = 0; nb < 16; nb++) {
            sacc[nb].x *= ATTN_SCALE; sacc[nb].y *= ATTN_SCALE;
            sacc[nb].z *= ATTN_SCALE; sacc[nb].w *= ATTN_SCALE;
            vmax0 = fmaxf(vmax0, fmaxf(sacc[nb].x, sacc[nb].y));
            vmax1 = fmaxf(vmax1, fmaxf(sacc[nb].z, sacc[nb].w));
        }
#pragma unroll
        for (int m = 1; m < 4; m <<= 1) {
            vmax0 = fmaxf(vmax0, __shfl_xor_sync(0xffffffffu, vmax0, m));
            vmax1 = fmaxf(vmax1, __shfl_xor_sync(0xffffffffu, vmax1, m));
        }
        float mnew0 = fmaxf(m0, vmax0);
        float mnew1 = fmaxf(m1, vmax1);
        float alpha0 = __expf(m0 - mnew0);
        float alpha1 = __expf(m1 - mnew1);
        float sum0 = 0.f, sum1 = 0.f;
#pragma unroll
        for (int nb = 0; nb < 16; nb++) {
            float px = __expf(sacc[nb].x - mnew0);
            float py = __expf(sacc[nb].y - mnew0);
            float pz = __expf(sacc[nb].z - mnew1);
            float pw = __expf(sacc[nb].w - mnew1);
            sum0 += px + py;  sum1 += pz + pw;
            int c0 = nb * 8 + 2 * lc;
            Ss[(r0)     * SS_PITCH + c0]     = f2tf(px);
            Ss[(r0)     * SS_PITCH + c0 + 1] = f2tf(py);
            Ss[(r0 + 8) * SS_PITCH + c0]     = f2tf(pz);
            Ss[(r0 + 8) * SS_PITCH + c0 + 1] = f2tf(pw);
        }
#pragma unroll
        for (int m = 1; m < 4; m <<= 1) {
            sum0 += __shfl_xor_sync(0xffffffffu, sum0, m);
            sum1 += __shfl_xor_sync(0xffffffffu, sum1, m);
        }
        l0 = l0 * alpha0 + sum0;  m0 = mnew0;
        l1 = l1 * alpha1 + sum1;  m1 = mnew1;

#pragma unroll
        for (int nb = 0; nb < 4; nb++) {
            o[nb].x *= alpha0; o[nb].y *= alpha0;
            o[nb].z *= alpha1; o[nb].w *= alpha1;
        }
        __syncthreads();

        if (kt < 7) {
#pragma unroll
            for (int i = 0; i < 4; i++) {
                int r = st_r + i * 32;
                float4 k = *(const float4*)&Kg[((kt + 1) * 128 + r) * HDIM + st_d4];
                Ks[r * KS_PITCH + st_d4 + 0] = f2tf(k.x);
                Ks[r * KS_PITCH + st_d4 + 1] = f2tf(k.y);
                Ks[r * KS_PITCH + st_d4 + 2] = f2tf(k.z);
                Ks[r * KS_PITCH + st_d4 + 3] = f2tf(k.w);
            }
        }

#pragma unroll
        for (int kb = 0; kb < 16; kb++) {
            uint32_t a0 = Ss[(r0)     * SS_PITCH + kb * 8 + lc];
            uint32_t a1 = Ss[(r0 + 8) * SS_PITCH + kb * 8 + lc];
            uint32_t a2 = Ss[(r0)     * SS_PITCH + kb * 8 + lc + 4];
            uint32_t a3 = Ss[(r0 + 8) * SS_PITCH + kb * 8 + lc + 4];
#pragma unroll
            for (int nb = 0; nb < 4; nb++) {
                uint32_t b0 = Vs[(kb * 8 + lc)     * VS_PITCH + nb * 8 + lr];
                uint32_t b1 = Vs[(kb * 8 + lc + 4) * VS_PITCH + nb * 8 + lr];
                mma_tf32(o[nb], a0, a1, a2, a3, b0, b1);
            }
        }
        __syncthreads();
    }

    float il0 = 1.f / l0, il1 = 1.f / l1;
#pragma unroll
    for (int nb = 0; nb < 4; nb++) {
        int c0 = nb * 8 + 2 * lc;
        Ssf[(r0)     * 33 + c0]     = o[nb].x * il0;
        Ssf[(r0)     * 33 + c0 + 1] = o[nb].y * il0;
        Ssf[(r0 + 8) * 33 + c0]     = o[nb].z * il1;
        Ssf[(r0 + 8) * 33 + c0 + 1] = o[nb].w * il1;
    }
    __syncthreads();
    float* outb = g_attn + (b * CCH + head * HDIM) * HWSZ + q0;
#pragma unroll
    for (int i = 0; i < 16; i++) {
        int idx = i * 256 + tid;
        int d = idx >> 7, r = idx & 127;
        outb[d * HWSZ + r] = Ssf[r * 33 + d];
    }
}

// =====================================================================
// GroupNorm stats (unchanged)
// =====================================================================
__global__ __launch_bounds__(256) void gn_stats_kernel()
{
    __shared__ float rs[8], rs2[8];
    int bg = blockIdx.x;
    const float4* p = (const float4*)(g_proj + (size_t)bg * 32 * HWSZ);
    float s = 0.f, s2 = 0.f;
    for (int i = threadIdx.x; i < 8192; i += 256) {
        float4 v = p[i];
        s  += v.x + v.y + v.z + v.w;
        s2 += v.x * v.x + v.y * v.y + v.z * v.z + v.w * v.w;
    }
#pragma unroll
    for (int m = 16; m >= 1; m >>= 1) {
        s  += __shfl_xor_sync(0xffffffffu, s, m);
        s2 += __shfl_xor_sync(0xffffffffu, s2, m);
    }
    int lane = threadIdx.x & 31, w = threadIdx.x >> 5;
    if (lane == 0) { rs[w] = s; rs2[w] = s2; }
    __syncthreads();
    if (threadIdx.x == 0) {
        float S = 0.f, S2 = 0.f;
#pragma unroll
        for (int i = 0; i < 8; i++) { S += rs[i]; S2 += rs2[i]; }
        float mean = S * (1.f / 32768.f);
        float var  = S2 * (1.f / 32768.f) - mean * mean;
        g_stats[bg] = make_float2(mean, rsqrtf(var + GN_EPS));
    }
}

// =====================================================================
// normalize + affine + residual (unchanged)
// =====================================================================
__global__ __launch_bounds__(256) void apply_kernel(const float4* __restrict__ x,
                                                    const float* __restrict__ gamma,
                                                    const float* __restrict__ beta,
                                                    float4* __restrict__ out)
{
    int i = blockIdx.x * 256 + threadIdx.x;
    int lin = i << 2;
    int c   = (lin >> 10) & 255;
    int bg  = lin >> 15;
    float2 st = g_stats[bg];
    float ga = gamma[c] * st.y;
    float be = beta[c];
    float4 pv = ((const float4*)g_proj)[i];
    float4 xv = x[i];
    float4 o;
    o.x = (pv.x - st.x) * ga + be + xv.x;
    o.y = (pv.y - st.x) * ga + be + xv.y;
    o.z = (pv.z - st.x) * ga + be + xv.z;
    o.w = (pv.w - st.x) * ga + be + xv.w;
    out[i] = o;
}

// =====================================================================
extern "C" void kernel_launch(void* const* d_in, const int* in_sizes, int n_in,
                              void* d_out, int out_size)
{
    const float* x      = (const float*)d_in[0];
    const float* w_qkv  = (const float*)d_in[1];
    const float* w_proj = (const float*)d_in[2];
    const float* gamma  = (const float*)d_in[3];
    const float* beta   = (const float*)d_in[4];
    float* out = (float*)d_out;

    cudaFuncSetAttribute(attn_kernel, cudaFuncAttributeMaxDynamicSharedMemorySize,
                         ATTN_SMEM_BYTES);
    cudaFuncSetAttribute(gemm_tc_kernel, cudaFuncAttributeMaxDynamicSharedMemorySize,
                         GEMM_SMEM_BYTES);

    gemm_tc_kernel<<<dim3(6, 8, 16), 256, GEMM_SMEM_BYTES>>>(w_qkv, x, 0);   // QKV
    attn_kernel<<<dim3(8, 8, 16), 256, ATTN_SMEM_BYTES>>>();                 // attention
    gemm_tc_kernel<<<dim3(2, 8, 16), 256, GEMM_SMEM_BYTES>>>(w_proj, x, 1);  // proj
    gn_stats_kernel<<<128, 256>>>();                                         // GN stats
    apply_kernel<<<4096, 256>>>((const float4*)x, gamma, beta,               // GN + residual
                                (float4*)out);
}